// round 2
// baseline (speedup 1.0000x reference)
#include <cuda_runtime.h>
#include <cuda_bf16.h>

#define BH 32
#define SEQ 8192
#define D 64
#define BK 64
#define NB 128   /* q buckets (rows) */
#define NC 129   /* kv buckets + 1 (cols) */

// Scratch (device globals — no allocation allowed in kernel_launch)
__device__ float4 g_Sq[BH*NB*16];   // per-bucket q sums        (64 floats/bucket)
__device__ float4 g_qF[BH*NB*16];   // first q element of bucket
__device__ float4 g_Sk[BH*NB*16];   // per-bucket k sums
__device__ float4 g_Wk[BH*NB*16];   // within-bucket weighted cum-k term
__device__ float4 g_sqT[BH*D*NB/4]; // final sq, transposed: [b][e][j], pre-scaled
__device__ float  g_skT[BH*D*NC];   // final sk, transposed: [b][e][col]

// ---------------------------------------------------------------------------
// Kernel A: stream q,k once with float4 loads. 128 threads / 8 buckets per
// block; thread = (bucket_local, float4-lane over e).
// ---------------------------------------------------------------------------
__global__ void __launch_bounds__(128) kA(const float4* __restrict__ q,
                                          const float4* __restrict__ k) {
    int t  = blockIdx.x * 128 + threadIdx.x;
    int gb = t >> 4;          // global bucket index = b*128 + j (rows contiguous)
    int l  = t & 15;          // float4 lane: e = 4*l .. 4*l+3
    int j  = gb & 127;
    int t0 = j << 6;

    const float4* qp = q + (size_t)gb * (BK * 16) + l;
    const float4* kp = k + (size_t)gb * (BK * 16) + l;

    float4 qf = qp[0];
    float4 rq = qf;
    float4 rk = kp[0];
    float  r0 = __fdividef(1.0f, (float)(t0 + 1));
    float4 wk = make_float4(rk.x * r0, rk.y * r0, rk.z * r0, rk.w * r0);

#pragma unroll 4
    for (int s = 1; s < BK; s++) {
        float4 qv = qp[s * 16];
        float4 kv = kp[s * 16];
        rq.x += qv.x; rq.y += qv.y; rq.z += qv.z; rq.w += qv.w;
        rk.x += kv.x; rk.y += kv.y; rk.z += kv.z; rk.w += kv.w;
        float rs = __fdividef(1.0f, (float)(t0 + s + 1));
        wk.x += rk.x * rs; wk.y += rk.y * rs;
        wk.z += rk.z * rs; wk.w += rk.w * rs;
    }
    int idx = gb * 16 + l;
    g_Sq[idx] = rq;
    g_qF[idx] = qf;
    g_Sk[idx] = rk;
    g_Wk[idx] = wk;
}

// ---------------------------------------------------------------------------
// Kernel B1: warp-parallel bucket prefix scans. Grid = BH*2 (b, which=q|k),
// 512 threads. Smem staged transposed [e][j] with pitch 132 (float4-aligned,
// conflict-light). Each warp scans 4 e-channels via shuffle scan.
// ---------------------------------------------------------------------------
__global__ void __launch_bounds__(512) kB1() {
    extern __shared__ float sm[];
    float* sA = sm;                 // [64][132] : S values transposed
    float* sB = sm + 64 * 132;      // [64][132] : qF or Wk transposed
    float* sH = sm + 2 * 64 * 132;  // [128]     : harmonic partials (k only)

    int b     = blockIdx.x >> 1;
    int which = blockIdx.x & 1;     // 0 = q, 1 = k
    int tid   = threadIdx.x;
    int base  = b * NB * 16;        // float4 index base

    const float* gS = (const float*)(which ? g_Sk : g_Sq);
    const float* gX = (const float*)(which ? g_Wk : g_qF);

    for (int idx = tid; idx < NB * D; idx += 512) {
        int j = idx >> 6, e = idx & 63;
        float vS = gS[base * 4 + idx];
        float vX = gX[base * 4 + idx];
        sA[e * 132 + j] = vS;
        sB[e * 132 + j] = vX;
    }
    if (which && tid < NB) {
        int t0 = tid * BK;
        float h = 0.0f;
#pragma unroll 8
        for (int s = 0; s < BK; s++)
            h += __fdividef(1.0f, (float)(t0 + s + 1));
        sH[tid] = h;
    }
    __syncthreads();

    int w = tid >> 5, lane = tid & 31;
#pragma unroll
    for (int c = 0; c < 4; c++) {
        int e = w * 4 + c;
        float4 v = *(const float4*)&sA[e * 132 + lane * 4];
        float s01 = v.x + v.y, s012 = s01 + v.z, lsum = s012 + v.w;

        // inclusive warp scan of lane sums -> exclusive prefix
        float run = lsum;
#pragma unroll
        for (int o = 1; o < 32; o <<= 1) {
            float tshf = __shfl_up_sync(0xffffffffu, run, o);
            if (lane >= o) run += tshf;
        }
        float excl = run - lsum;
        float p0 = excl, p1 = excl + v.x, p2 = excl + s01, p3 = excl + s012;
        int j0 = lane * 4;

        float4 xb = *(const float4*)&sB[e * 132 + j0];
        if (!which) {
            // sq[j] = (P + qfirst) * (0.125 / (j*64+1)), stored transposed
            float4 o4;
            o4.x = (p0 + xb.x) * __fdividef(0.125f, (float)(j0 * 64 + 1));
            o4.y = (p1 + xb.y) * __fdividef(0.125f, (float)((j0 + 1) * 64 + 1));
            o4.z = (p2 + xb.z) * __fdividef(0.125f, (float)((j0 + 2) * 64 + 1));
            o4.w = (p3 + xb.w) * __fdividef(0.125f, (float)((j0 + 3) * 64 + 1));
            g_sqT[(size_t)(b * 64 + e) * 32 + lane] = o4;
        } else {
            // sk[j] = P*H[j] + W[j], leading zero column, stored transposed
            float* dst = g_skT + (size_t)(b * 64 + e) * NC;
            if (lane == 0) dst[0] = 0.0f;
            dst[j0 + 1] = p0 * sH[j0]     + xb.x;
            dst[j0 + 2] = p1 * sH[j0 + 1] + xb.y;
            dst[j0 + 3] = p2 * sH[j0 + 2] + xb.z;
            dst[j0 + 4] = p3 * sH[j0 + 3] + xb.w;
        }
    }
}

// ---------------------------------------------------------------------------
// Kernel B2: GEMM + masked softmax + strict-lower-triangle output.
// One block per (b, 16-row tile); each warp handles 2 rows, 5 cols per lane.
// ---------------------------------------------------------------------------
__global__ void __launch_bounds__(256) kB2(float* __restrict__ out) {
    __shared__ float skT[D][NC + 3];   // [64][132]
    __shared__ float sqs[16][65];

    int b    = blockIdx.x >> 3;
    int tile = blockIdx.x & 7;
    int i0   = tile * 16;
    int tid  = threadIdx.x;
    int w    = tid >> 5, lane = tid & 31;

    // stage skT rows: warp-strided, no integer division
    {
        const float* src = g_skT + (size_t)b * D * NC;
        for (int e = w; e < D; e += 8)
            for (int c = lane; c < NC; c += 32)
                skT[e][c] = src[e * NC + c];
    }
    // stage sq tile from transposed layout
    {
        const float* srcq = (const float*)g_sqT;
        for (int idx = tid; idx < 16 * D; idx += 256) {
            int e = idx >> 4, jl = idx & 15;
            sqs[jl][e] = srcq[(size_t)(b * 64 + e) * NB + i0 + jl];
        }
    }
    __syncthreads();

#pragma unroll
    for (int rr = 0; rr < 2; rr++) {
        int rl = w * 2 + rr;
        int i  = i0 + rl;

        float a0 = 0.f, a1 = 0.f, a2 = 0.f, a3 = 0.f, a4 = 0.f;
#pragma unroll 8
        for (int e = 0; e < D; e++) {
            float a = sqs[rl][e];          // broadcast
            a0 += a * skT[e][lane];
            a1 += a * skT[e][lane + 32];
            a2 += a * skT[e][lane + 64];
            a3 += a * skT[e][lane + 96];
            a4 += a * skT[e][128];         // broadcast; only lane 0's is used
        }

        float v[5] = {a0, a1, a2, a3, a4};
        float m = -3.402823466e+38f;
#pragma unroll
        for (int c = 0; c < 5; c++) {
            int jj = lane + 32 * c;
            if (jj <= i) m = fmaxf(m, v[c]);
        }
#pragma unroll
        for (int o = 16; o; o >>= 1)
            m = fmaxf(m, __shfl_xor_sync(0xffffffffu, m, o));

        float s = 0.0f;
#pragma unroll
        for (int c = 0; c < 5; c++) {
            int jj = lane + 32 * c;
            float ex = (jj <= i) ? __expf(v[c] - m) : 0.0f;
            v[c] = ex;
            s += ex;
        }
#pragma unroll
        for (int o = 16; o; o >>= 1)
            s += __shfl_xor_sync(0xffffffffu, s, o);
        float inv = __fdividef(1.0f, s);

        float* orow = out + ((size_t)(b * NB + i)) * NC;
#pragma unroll
        for (int c = 0; c < 5; c++) {
            int jj = lane + 32 * c;
            if (jj < NC) orow[jj] = (jj < i) ? v[c] * inv : 0.0f;
        }
    }
}

// ---------------------------------------------------------------------------
extern "C" void kernel_launch(void* const* d_in, const int* in_sizes, int n_in,
                              void* d_out, int out_size) {
    const float4* q = (const float4*)d_in[0];
    const float4* k = (const float4*)d_in[1];
    float* out = (float*)d_out;

    int smemB1 = (2 * 64 * 132 + 128) * (int)sizeof(float);
    cudaFuncSetAttribute(kB1, cudaFuncAttributeMaxDynamicSharedMemorySize, smemB1);

    kA<<<BH * NB * 16 / 128, 128>>>(q, k);
    kB1<<<BH * 2, 512, smemB1>>>();
    kB2<<<BH * 8, 256>>>(out);
}

// round 3
// speedup vs baseline: 1.0849x; 1.0849x over previous
#include <cuda_runtime.h>
#include <cuda_bf16.h>

#define BH 32
#define SEQ 8192
#define D 64
#define BK 64
#define NB 128   /* q buckets (rows) */
#define NC 129   /* kv buckets + 1 (cols) */

// ---------------------------------------------------------------------------
// Compile-time tables (double-accumulated, stored float):
//  cw[t]  = sum_{s=u..63} 1/(t0+s+1)  (suffix harmonic within t's bucket)
//  sH[j]  = sum_{s=0..63} 1/(j*64+s+1)
//  rq0[j] = 0.125 / (j*64+1)
// ---------------------------------------------------------------------------
struct Tables {
    float cw[SEQ];
    float sH[NB];
    float rq0[NB];
};
constexpr Tables make_tables() {
    Tables t{};
    for (int j = 0; j < NB; j++) {
        double acc = 0.0;
        for (int s = BK - 1; s >= 0; s--) {
            acc += 1.0 / (double)(j * BK + s + 1);
            t.cw[j * BK + s] = (float)acc;
        }
        t.sH[j]  = (float)acc;
        t.rq0[j] = (float)(0.125 / (double)(j * BK + 1));
    }
    return t;
}
__device__ const Tables c_tab = make_tables();

// Scratch (device globals — no allocation allowed in kernel_launch)
__device__ float4 g_Sq[BH*NB*16];   // per-bucket q sums
__device__ float4 g_qF[BH*NB*16];   // first q element of bucket
__device__ float4 g_Sk[BH*NB*16];   // per-bucket k sums
__device__ float4 g_Wk[BH*NB*16];   // full within-bucket weighted term W[j]
__device__ float4 g_sqT[BH*D*NB/4]; // final sq, transposed [b][e][j], pre-scaled
__device__ float  g_skT[BH*D*NC];   // final sk, transposed [b][e][col]

// ---------------------------------------------------------------------------
// Kernel A: stream q,k once. 262144 threads; each bucket split over 4 subs
// of 16 steps, 16 float4 e-lanes. No serial cross-step dependency (weights
// come from cw table), so partials combine via smem.
// ---------------------------------------------------------------------------
__global__ void __launch_bounds__(256) kA(const float4* __restrict__ q,
                                          const float4* __restrict__ k) {
    __shared__ float4 sRq[4][4][16];
    __shared__ float4 sRk[4][4][16];
    __shared__ float4 sWp[4][4][16];
    __shared__ float4 sQf[4][16];

    int tid = threadIdx.x;
    int bl  = tid >> 6;            // bucket within block (0..3)
    int r   = tid & 63;
    int sub = r >> 4;              // 0..3 (16 steps each)
    int l   = r & 15;              // float4 lane over e
    int gb  = blockIdx.x * 4 + bl; // global bucket = b*128 + j
    int t0s = (gb & 127) * BK + sub * 16;  // global t of first step

    const float4* qp = q + (size_t)gb * (BK * 16) + (size_t)sub * (16 * 16) + l;
    const float4* kp = k + (size_t)gb * (BK * 16) + (size_t)sub * (16 * 16) + l;
    const float4* cw4 = (const float4*)(c_tab.cw + t0s);

    float4 rq = make_float4(0.f, 0.f, 0.f, 0.f);
    float4 rk = rq, wp = rq;
    float4 qf;

#pragma unroll 4
    for (int s = 0; s < 16; s++) {
        float4 qv = qp[s * 16];
        float4 kv = kp[s * 16];
        if (s == 0 && sub == 0) qf = qv;
        float w = ((const float*)cw4)[s];
        rq.x += qv.x; rq.y += qv.y; rq.z += qv.z; rq.w += qv.w;
        rk.x += kv.x; rk.y += kv.y; rk.z += kv.z; rk.w += kv.w;
        wp.x += kv.x * w; wp.y += kv.y * w; wp.z += kv.z * w; wp.w += kv.w * w;
    }

    sRq[bl][sub][l] = rq;
    sRk[bl][sub][l] = rk;
    sWp[bl][sub][l] = wp;
    if (sub == 0) sQf[bl][l] = qf;
    __syncthreads();

    if (sub == 0) {
        float4 a = sRq[bl][0][l], b4 = sRq[bl][1][l],
               c = sRq[bl][2][l], d4 = sRq[bl][3][l];
        float4 RQ = make_float4(a.x+b4.x+c.x+d4.x, a.y+b4.y+c.y+d4.y,
                                a.z+b4.z+c.z+d4.z, a.w+b4.w+c.w+d4.w);
        a = sRk[bl][0][l]; b4 = sRk[bl][1][l]; c = sRk[bl][2][l]; d4 = sRk[bl][3][l];
        float4 RK = make_float4(a.x+b4.x+c.x+d4.x, a.y+b4.y+c.y+d4.y,
                                a.z+b4.z+c.z+d4.z, a.w+b4.w+c.w+d4.w);
        a = sWp[bl][0][l]; b4 = sWp[bl][1][l]; c = sWp[bl][2][l]; d4 = sWp[bl][3][l];
        float4 WP = make_float4(a.x+b4.x+c.x+d4.x, a.y+b4.y+c.y+d4.y,
                                a.z+b4.z+c.z+d4.z, a.w+b4.w+c.w+d4.w);
        int idx = gb * 16 + l;
        g_Sq[idx] = RQ;
        g_Sk[idx] = RK;
        g_Wk[idx] = WP;
        g_qF[idx] = sQf[bl][l];
    }
}

// ---------------------------------------------------------------------------
// Kernel B1: warp-parallel bucket prefix scans (128 long). Grid = BH*2
// (b, which=q|k), 512 threads. Transposed smem staging, shuffle scans.
// All weights from compile-time tables — zero MUFU.
// ---------------------------------------------------------------------------
__global__ void __launch_bounds__(512) kB1() {
    extern __shared__ float sm[];
    float* sA = sm;                 // [64][132] : bucket sums, transposed
    float* sB = sm + 64 * 132;      // [64][132] : qF or W, transposed

    int b     = blockIdx.x >> 1;
    int which = blockIdx.x & 1;     // 0 = q, 1 = k
    int tid   = threadIdx.x;
    int base  = b * NB * 64;        // float index base

    const float* gS = (const float*)(which ? g_Sk : g_Sq);
    const float* gX = (const float*)(which ? g_Wk : g_qF);

    for (int idx = tid; idx < NB * D; idx += 512) {
        int j = idx >> 6, e = idx & 63;
        sA[e * 132 + j] = gS[base + idx];
        sB[e * 132 + j] = gX[base + idx];
    }
    __syncthreads();

    int w = tid >> 5, lane = tid & 31;
#pragma unroll
    for (int c = 0; c < 4; c++) {
        int e = w * 4 + c;
        float4 v = *(const float4*)&sA[e * 132 + lane * 4];
        float s01 = v.x + v.y, s012 = s01 + v.z, lsum = s012 + v.w;

        float run = lsum;
#pragma unroll
        for (int o = 1; o < 32; o <<= 1) {
            float tshf = __shfl_up_sync(0xffffffffu, run, o);
            if (lane >= o) run += tshf;
        }
        float excl = run - lsum;
        float p0 = excl, p1 = excl + v.x, p2 = excl + s01, p3 = excl + s012;
        int j0 = lane * 4;

        float4 xb = *(const float4*)&sB[e * 132 + j0];
        if (!which) {
            float4 o4;
            o4.x = (p0 + xb.x) * c_tab.rq0[j0];
            o4.y = (p1 + xb.y) * c_tab.rq0[j0 + 1];
            o4.z = (p2 + xb.z) * c_tab.rq0[j0 + 2];
            o4.w = (p3 + xb.w) * c_tab.rq0[j0 + 3];
            g_sqT[(size_t)(b * 64 + e) * 32 + lane] = o4;
        } else {
            float* dst = g_skT + (size_t)(b * 64 + e) * NC;
            if (lane == 0) dst[0] = 0.0f;
            dst[j0 + 1] = p0 * c_tab.sH[j0]     + xb.x;
            dst[j0 + 2] = p1 * c_tab.sH[j0 + 1] + xb.y;
            dst[j0 + 3] = p2 * c_tab.sH[j0 + 2] + xb.z;
            dst[j0 + 4] = p3 * c_tab.sH[j0 + 3] + xb.w;
        }
    }
}

// ---------------------------------------------------------------------------
// Kernel B2: GEMM + masked softmax + strict-lower-triangle output.
// One block per (b, 16-row tile); each warp 2 rows, 5 cols per lane.
// ---------------------------------------------------------------------------
__global__ void __launch_bounds__(256) kB2(float* __restrict__ out) {
    __shared__ float skT[D][NC + 3];   // [64][132]
    __shared__ float sqs[16][65];

    int b    = blockIdx.x >> 3;
    int tile = blockIdx.x & 7;
    int i0   = tile * 16;
    int tid  = threadIdx.x;
    int w    = tid >> 5, lane = tid & 31;

    {
        const float* src = g_skT + (size_t)b * D * NC;
        for (int e = w; e < D; e += 8)
            for (int c = lane; c < NC; c += 32)
                skT[e][c] = src[e * NC + c];
    }
    {
        const float* srcq = (const float*)g_sqT;
        for (int idx = tid; idx < 16 * D; idx += 256) {
            int e = idx >> 4, jl = idx & 15;
            sqs[jl][e] = srcq[(size_t)(b * 64 + e) * NB + i0 + jl];
        }
    }
    __syncthreads();

#pragma unroll
    for (int rr = 0; rr < 2; rr++) {
        int rl = w * 2 + rr;
        int i  = i0 + rl;

        float a0 = 0.f, a1 = 0.f, a2 = 0.f, a3 = 0.f, a4 = 0.f;
#pragma unroll 8
        for (int e = 0; e < D; e++) {
            float a = sqs[rl][e];
            a0 += a * skT[e][lane];
            a1 += a * skT[e][lane + 32];
            a2 += a * skT[e][lane + 64];
            a3 += a * skT[e][lane + 96];
            a4 += a * skT[e][128];
        }

        float v[5] = {a0, a1, a2, a3, a4};
        float m = -3.402823466e+38f;
#pragma unroll
        for (int c = 0; c < 5; c++) {
            int jj = lane + 32 * c;
            if (jj <= i) m = fmaxf(m, v[c]);
        }
#pragma unroll
        for (int o = 16; o; o >>= 1)
            m = fmaxf(m, __shfl_xor_sync(0xffffffffu, m, o));

        float s = 0.0f;
#pragma unroll
        for (int c = 0; c < 5; c++) {
            int jj = lane + 32 * c;
            float ex = (jj <= i) ? __expf(v[c] - m) : 0.0f;
            v[c] = ex;
            s += ex;
        }
#pragma unroll
        for (int o = 16; o; o >>= 1)
            s += __shfl_xor_sync(0xffffffffu, s, o);
        float inv = __fdividef(1.0f, s);

        float* orow = out + ((size_t)(b * NB + i)) * NC;
#pragma unroll
        for (int c = 0; c < 5; c++) {
            int jj = lane + 32 * c;
            if (jj < NC) orow[jj] = (jj < i) ? v[c] * inv : 0.0f;
        }
    }
}

// ---------------------------------------------------------------------------
extern "C" void kernel_launch(void* const* d_in, const int* in_sizes, int n_in,
                              void* d_out, int out_size) {
    const float4* q = (const float4*)d_in[0];
    const float4* k = (const float4*)d_in[1];
    float* out = (float*)d_out;

    int smemB1 = (2 * 64 * 132) * (int)sizeof(float);
    cudaFuncSetAttribute(kB1, cudaFuncAttributeMaxDynamicSharedMemorySize, smemB1);

    kA<<<BH * NB / 4, 256>>>(q, k);
    kB1<<<BH * 2, 512, smemB1>>>();
    kB2<<<BH * 8, 256>>>(out);
}

// round 4
// speedup vs baseline: 1.2084x; 1.1138x over previous
#include <cuda_runtime.h>
#include <cuda_bf16.h>

#define BH 32
#define SEQ 8192
#define D 64
#define BK 64
#define NB 128   /* q buckets (rows) */
#define NC 129   /* kv buckets + 1 (cols) */
#define PITCH 132

// ---------------------------------------------------------------------------
// Compile-time tables (double-accumulated, stored float):
//  cw[t]  = suffix harmonic within t's bucket:  sum_{s=u..63} 1/(j*64+s+1)
//  sH[j]  = sum_{s=0..63} 1/(j*64+s+1)
//  rq0[j] = 0.125 / (j*64+1)
// ---------------------------------------------------------------------------
struct Tables {
    float cw[SEQ];
    float sH[NB];
    float rq0[NB];
};
constexpr Tables make_tables() {
    Tables t{};
    for (int j = 0; j < NB; j++) {
        double acc = 0.0;
        for (int s = BK - 1; s >= 0; s--) {
            acc += 1.0 / (double)(j * BK + s + 1);
            t.cw[j * BK + s] = (float)acc;
        }
        t.sH[j]  = (float)acc;
        t.rq0[j] = (float)(0.125 / (double)(j * BK + 1));
    }
    return t;
}
__device__ const Tables c_tab = make_tables();

// Scratch (device globals)
__device__ float4 g_Sq[BH*NB*16];   // per-bucket q sums
__device__ float4 g_Sk[BH*NB*16];   // per-bucket k sums
__device__ float4 g_Wk[BH*NB*16];   // within-bucket weighted k term W[j]

// ---------------------------------------------------------------------------
// Kernel A: stream q,k once. Bucket split over 4 subs x 16 float4-lanes;
// weights from cw table kill the serial dependency.
// ---------------------------------------------------------------------------
__global__ void __launch_bounds__(256) kA(const float4* __restrict__ q,
                                          const float4* __restrict__ k) {
    __shared__ float4 sRq[4][4][16];
    __shared__ float4 sRk[4][4][16];
    __shared__ float4 sWp[4][4][16];

    int tid = threadIdx.x;
    int bl  = tid >> 6;
    int r   = tid & 63;
    int sub = r >> 4;
    int l   = r & 15;
    int gb  = blockIdx.x * 4 + bl;
    int t0s = (gb & 127) * BK + sub * 16;

    const float4* qp = q + (size_t)gb * 1024 + sub * 256 + l;
    const float4* kp = k + (size_t)gb * 1024 + sub * 256 + l;
    const float*  cw = c_tab.cw + t0s;

    float4 rq = make_float4(0.f, 0.f, 0.f, 0.f);
    float4 rk = rq, wp = rq;

#pragma unroll 8
    for (int s = 0; s < 16; s++) {
        float4 qv = qp[s * 16];
        float4 kv = kp[s * 16];
        float  w  = cw[s];
        rq.x += qv.x; rq.y += qv.y; rq.z += qv.z; rq.w += qv.w;
        rk.x += kv.x; rk.y += kv.y; rk.z += kv.z; rk.w += kv.w;
        wp.x += kv.x * w; wp.y += kv.y * w; wp.z += kv.z * w; wp.w += kv.w * w;
    }

    sRq[bl][sub][l] = rq;
    sRk[bl][sub][l] = rk;
    sWp[bl][sub][l] = wp;
    __syncthreads();

    if (sub == 0) {
        float4 a, b4, c, d4;
        a = sRq[bl][0][l]; b4 = sRq[bl][1][l]; c = sRq[bl][2][l]; d4 = sRq[bl][3][l];
        g_Sq[gb * 16 + l] = make_float4(a.x+b4.x+c.x+d4.x, a.y+b4.y+c.y+d4.y,
                                        a.z+b4.z+c.z+d4.z, a.w+b4.w+c.w+d4.w);
        a = sRk[bl][0][l]; b4 = sRk[bl][1][l]; c = sRk[bl][2][l]; d4 = sRk[bl][3][l];
        g_Sk[gb * 16 + l] = make_float4(a.x+b4.x+c.x+d4.x, a.y+b4.y+c.y+d4.y,
                                        a.z+b4.z+c.z+d4.z, a.w+b4.w+c.w+d4.w);
        a = sWp[bl][0][l]; b4 = sWp[bl][1][l]; c = sWp[bl][2][l]; d4 = sWp[bl][3][l];
        g_Wk[gb * 16 + l] = make_float4(a.x+b4.x+c.x+d4.x, a.y+b4.y+c.y+d4.y,
                                        a.z+b4.z+c.z+d4.z, a.w+b4.w+c.w+d4.w);
    }
}

// ---------------------------------------------------------------------------
// Kernel B (fused scans + GEMM + softmax + output).
// Grid = BH*4: block = (b, 32-row tile). 512 threads = 16 warps.
// All scans done in smem per block (redundant across the 4 tiles of a b, but
// cheap); no intermediate global round-trip.
// ---------------------------------------------------------------------------
__global__ void __launch_bounds__(512) kB(const float* __restrict__ q,
                                          float* __restrict__ out) {
    extern __shared__ float sm[];
    float* sA  = sm;                  // [64][132] staging (sums, transposed)
    float* sB  = sm + 64 * PITCH;     // [64][132] staging (W / qFirst)
    float* skT = sm + 2 * 64 * PITCH; // [64][132] final sk transposed, col 0..128
    float* sqs = sm + 3 * 64 * PITCH; // [32][65]  sq rows of this tile

    int b    = blockIdx.x >> 2;
    int tile = blockIdx.x & 3;
    int i0   = tile * 32;
    int tid  = threadIdx.x;
    int w    = tid >> 5, lane = tid & 31;

    // ---- stage k sums + W, transposed ----
    const float* gSk = (const float*)g_Sk + b * NB * D;
    const float* gWk = (const float*)g_Wk + b * NB * D;
    for (int idx = tid; idx < NB * D; idx += 512) {
        int j = idx >> 6, e = idx & 63;
        sA[e * PITCH + j] = gSk[idx];
        sB[e * PITCH + j] = gWk[idx];
    }
    __syncthreads();

    // ---- k scan: each warp owns 4 e-channels ----
#pragma unroll
    for (int c = 0; c < 4; c++) {
        int e = w * 4 + c;
        float4 v = *(const float4*)&sA[e * PITCH + lane * 4];
        float s01 = v.x + v.y, s012 = s01 + v.z, lsum = s012 + v.w;
        float run = lsum;
#pragma unroll
        for (int o = 1; o < 32; o <<= 1) {
            float tshf = __shfl_up_sync(0xffffffffu, run, o);
            if (lane >= o) run += tshf;
        }
        float excl = run - lsum;
        float p0 = excl, p1 = excl + v.x, p2 = excl + s01, p3 = excl + s012;
        int j0 = lane * 4;
        float4 xb = *(const float4*)&sB[e * PITCH + j0];
        if (lane == 0) skT[e * PITCH] = 0.0f;
        skT[e * PITCH + j0 + 1] = p0 * c_tab.sH[j0]     + xb.x;
        skT[e * PITCH + j0 + 2] = p1 * c_tab.sH[j0 + 1] + xb.y;
        skT[e * PITCH + j0 + 3] = p2 * c_tab.sH[j0 + 2] + xb.z;
        skT[e * PITCH + j0 + 4] = p3 * c_tab.sH[j0 + 3] + xb.w;
    }
    __syncthreads();

    // ---- restage: q sums + q bucket-first (directly from q) ----
    const float* gSq = (const float*)g_Sq + b * NB * D;
    const float* qb  = q + (size_t)b * SEQ * D;
    for (int idx = tid; idx < NB * D; idx += 512) {
        int j = idx >> 6, e = idx & 63;
        sA[e * PITCH + j] = gSq[idx];
        sB[e * PITCH + j] = qb[(size_t)j * (BK * D) + e];
    }
    __syncthreads();

    // ---- q scan; keep only this tile's 32 rows ----
#pragma unroll
    for (int c = 0; c < 4; c++) {
        int e = w * 4 + c;
        float4 v = *(const float4*)&sA[e * PITCH + lane * 4];
        float s01 = v.x + v.y, s012 = s01 + v.z, lsum = s012 + v.w;
        float run = lsum;
#pragma unroll
        for (int o = 1; o < 32; o <<= 1) {
            float tshf = __shfl_up_sync(0xffffffffu, run, o);
            if (lane >= o) run += tshf;
        }
        float excl = run - lsum;
        int j0 = lane * 4;
        if (j0 >= i0 && j0 < i0 + 32) {
            float p0 = excl, p1 = excl + v.x, p2 = excl + s01, p3 = excl + s012;
            float4 xb = *(const float4*)&sB[e * PITCH + j0];
            int r0 = j0 - i0;
            sqs[(r0    ) * 65 + e] = (p0 + xb.x) * c_tab.rq0[j0];
            sqs[(r0 + 1) * 65 + e] = (p1 + xb.y) * c_tab.rq0[j0 + 1];
            sqs[(r0 + 2) * 65 + e] = (p2 + xb.z) * c_tab.rq0[j0 + 2];
            sqs[(r0 + 3) * 65 + e] = (p3 + xb.w) * c_tab.rq0[j0 + 3];
        }
    }
    __syncthreads();

    // ---- GEMM: 16 warps x 2 rows, skT loads shared across the row pair ----
    int rl0 = w * 2, rl1 = rl0 + 1;
    float acc[2][5] = {{0,0,0,0,0},{0,0,0,0,0}};
#pragma unroll 8
    for (int e = 0; e < D; e++) {
        float a0 = sqs[rl0 * 65 + e];
        float a1 = sqs[rl1 * 65 + e];
        float b0 = skT[e * PITCH + lane];
        float b1 = skT[e * PITCH + lane + 32];
        float b2 = skT[e * PITCH + lane + 64];
        float b3 = skT[e * PITCH + lane + 96];
        float b4 = skT[e * PITCH + 128];
        acc[0][0] += a0 * b0; acc[1][0] += a1 * b0;
        acc[0][1] += a0 * b1; acc[1][1] += a1 * b1;
        acc[0][2] += a0 * b2; acc[1][2] += a1 * b2;
        acc[0][3] += a0 * b3; acc[1][3] += a1 * b3;
        acc[0][4] += a0 * b4; acc[1][4] += a1 * b4;
    }

#pragma unroll
    for (int rr = 0; rr < 2; rr++) {
        int i = i0 + rl0 + rr;
        float* v = acc[rr];

        float m = -3.402823466e+38f;
#pragma unroll
        for (int c = 0; c < 5; c++) {
            int jj = lane + 32 * c;
            if (jj <= i) m = fmaxf(m, v[c]);
        }
#pragma unroll
        for (int o = 16; o; o >>= 1)
            m = fmaxf(m, __shfl_xor_sync(0xffffffffu, m, o));

        float s = 0.0f;
#pragma unroll
        for (int c = 0; c < 5; c++) {
            int jj = lane + 32 * c;
            float ex = (jj <= i) ? __expf(v[c] - m) : 0.0f;
            v[c] = ex;
            s += ex;
        }
#pragma unroll
        for (int o = 16; o; o >>= 1)
            s += __shfl_xor_sync(0xffffffffu, s, o);
        float inv = __fdividef(1.0f, s);

        float* orow = out + ((size_t)(b * NB + i)) * NC;
#pragma unroll
        for (int c = 0; c < 5; c++) {
            int jj = lane + 32 * c;
            if (jj < NC) orow[jj] = (jj < i) ? v[c] * inv : 0.0f;
        }
    }
}

// ---------------------------------------------------------------------------
extern "C" void kernel_launch(void* const* d_in, const int* in_sizes, int n_in,
                              void* d_out, int out_size) {
    const float4* q4 = (const float4*)d_in[0];
    const float4* k4 = (const float4*)d_in[1];
    const float*  qf = (const float*)d_in[0];
    float* out = (float*)d_out;

    int smemB = (3 * 64 * PITCH + 32 * 65) * (int)sizeof(float);
    cudaFuncSetAttribute(kB, cudaFuncAttributeMaxDynamicSharedMemorySize, smemB);

    kA<<<BH * NB / 4, 256>>>(q4, k4);
    kB<<<BH * 4, 512, smemB>>>(qf, out);
}